// round 4
// baseline (speedup 1.0000x reference)
#include <cuda_runtime.h>
#include <math.h>

typedef unsigned long long ull;

#define CB 32
#define CT 40
#define CP 12
#define CE 2048
#define CH 1024
#define CM (CB*CT*CP)     /* 15360 rows of (b,t,p) */
#define CBP (CB*CP)       /* 384 GRU state rows */

/* ---------------- scratch (device globals; no allocation allowed) -------- */
__device__ float g_x  [CM * CH];        /* embed output, 63 MB  */
__device__ float g_gx [CM * 3 * CH];    /* input gates, 189 MB  */
__device__ float g_hid[CM * CH];        /* all hiddens, 63 MB   */
__device__ float g_h0 [CBP * CH];
__device__ float g_h1 [CBP * CH];

/* ---------------- packed fp32x2 FMA (Blackwell FFMA2) -------------------- */
__device__ __forceinline__ void ffma2(ull& d, ull a, ull b) {
    asm("fma.rn.f32x2 %0, %1, %2, %0;" : "+l"(d) : "l"(a), "l"(b));
}
__device__ __forceinline__ float2 upk(ull v) {
    return *reinterpret_cast<float2*>(&v);
}

/* ---------------- generic GEMM: C[m,n] = act(A[m,:]·W[n,:] + bias[n]) ----
 * A: [M,K] row-major, W: [N,K] row-major. BM=BN=128, BK=8, 256 threads,
 * 8x8 outputs/thread as 8 m x 4 n-pairs in f32x2 accumulators.
 * A stored duplicated in smem so FFMA2 needs no packing MOVs.
 * Register prefetch hides gmem latency.                                    */
#define BM 128
#define BN 128
#define BKc 8

__global__ __launch_bounds__(256) void gemm_f32x2(
    const float* __restrict__ A, const float* __restrict__ W,
    const float* __restrict__ bias, float* __restrict__ C,
    int M, int N, int K, int act)
{
    __shared__ __align__(16) float As[BKc][2*BM + 8];  /* duplicated pairs */
    __shared__ __align__(16) float Bs[BKc][BN + 4];

    const int tid = threadIdx.x;
    const int tx  = tid & 15;          /* n-group: cols tx*8..tx*8+7 */
    const int ty  = tid >> 4;          /* m-group: rows ty*8..ty*8+7 */
    const int lr  = tid >> 1;          /* loader row 0..127          */
    const int lk  = (tid & 1) << 2;    /* loader k offset 0 or 4     */

    const float* Ag = A + (size_t)(blockIdx.y * BM + lr) * K + lk;
    const float* Wg = W + (size_t)(blockIdx.x * BN + lr) * K + lk;

    ull acc[8][4];
#pragma unroll
    for (int i = 0; i < 8; i++)
#pragma unroll
        for (int j = 0; j < 4; j++) acc[i][j] = 0ULL;

    float4 pa = *(const float4*)Ag;
    float4 pb = *(const float4*)Wg;

    const int nch = K / BKc;
    for (int c = 0; c < nch; ++c) {
        __syncthreads();
        *(float2*)&As[lk+0][2*lr] = make_float2(pa.x, pa.x);
        *(float2*)&As[lk+1][2*lr] = make_float2(pa.y, pa.y);
        *(float2*)&As[lk+2][2*lr] = make_float2(pa.z, pa.z);
        *(float2*)&As[lk+3][2*lr] = make_float2(pa.w, pa.w);
        Bs[lk+0][lr] = pb.x;
        Bs[lk+1][lr] = pb.y;
        Bs[lk+2][lr] = pb.z;
        Bs[lk+3][lr] = pb.w;
        __syncthreads();
        if (c + 1 < nch) {                 /* prefetch next chunk to regs */
            pa = *(const float4*)(Ag + (size_t)(c+1)*BKc);
            pb = *(const float4*)(Wg + (size_t)(c+1)*BKc);
        }
#pragma unroll
        for (int kk = 0; kk < BKc; ++kk) {
            const ulonglong2* ap = (const ulonglong2*)&As[kk][ty*16];
            ulonglong2 a01 = ap[0], a23 = ap[1], a45 = ap[2], a67 = ap[3];
            const ulonglong2* bp = (const ulonglong2*)&Bs[kk][tx*8];
            ulonglong2 b01 = bp[0], b23 = bp[1];
            ull ad[8] = {a01.x, a01.y, a23.x, a23.y, a45.x, a45.y, a67.x, a67.y};
            ull bd[4] = {b01.x, b01.y, b23.x, b23.y};
#pragma unroll
            for (int i = 0; i < 8; i++)
#pragma unroll
                for (int j = 0; j < 4; j++) ffma2(acc[i][j], ad[i], bd[j]);
        }
    }

    const int row0 = blockIdx.y * BM + ty * 8;
    const int col0 = blockIdx.x * BN + tx * 8;
    float2 bb[4];
#pragma unroll
    for (int j = 0; j < 4; j++) bb[j] = *(const float2*)&bias[col0 + 2*j];
#pragma unroll
    for (int i = 0; i < 8; i++) {
        float* Cr = C + (size_t)(row0 + i) * N + col0;
#pragma unroll
        for (int j = 0; j < 4; j++) {
            float2 v = upk(acc[i][j]);
            v.x += bb[j].x;  v.y += bb[j].y;
            if (act) { v.x = tanhf(v.x); v.y = tanhf(v.y); }
            *(float2*)&Cr[2*j] = v;
        }
    }
}

/* ---------------- fused GRU step ----------------------------------------
 * Block computes gh = h_in · W_hh^T for a 32-row x 32-col tile, all 3 gates
 * gathered (B rows g*H+j), then applies the GRU update elementwise.
 * 256 threads: ty=tid/32 -> rows ty*4..+3 (2 f32x2 m-pairs), tx=j offset.
 * h double-buffered across steps. Writes h_out and hiddens[t].            */
#define GM 32
#define GN 32

__global__ __launch_bounds__(256) void gru_step(
    const float* __restrict__ h_in, float* __restrict__ h_out,
    const float* __restrict__ gx, const float* __restrict__ W_hh,
    const float* __restrict__ b_hh, float* __restrict__ hid, int t)
{
    __shared__ __align__(16) float As[BKc][GM + 4];      /* h tile, [k][m]    */
    __shared__ __align__(16) float Bs[BKc][2*96 + 8];    /* W tile, dup pairs */

    const int tid = threadIdx.x;
    const int tx  = tid & 31;          /* j within tile  */
    const int ty  = tid >> 5;          /* 0..7 row group */
    const int m0  = blockIdx.y * GM;
    const int j0  = blockIdx.x * GN;

    const int alr = tid >> 1, alk = (tid & 1) << 2;
    const float* Ag = h_in + (size_t)(m0 + alr) * CH + alk;          /* tid<64  */
    const float* Wg;
    {
        int g = alr >> 5;
        int j = j0 + (alr & 31);
        Wg = W_hh + (size_t)(g * CH + j) * CH + alk;                 /* tid<192 */
    }

    ull acc[2][3];
#pragma unroll
    for (int i = 0; i < 2; i++)
#pragma unroll
        for (int g = 0; g < 3; g++) acc[i][g] = 0ULL;

    float4 pa, pb;
    if (tid < 64)  pa = *(const float4*)Ag;
    if (tid < 192) pb = *(const float4*)Wg;

    const int nch = CH / BKc;   /* 128 */
    for (int c = 0; c < nch; ++c) {
        __syncthreads();
        if (tid < 64) {
            As[alk+0][alr] = pa.x;
            As[alk+1][alr] = pa.y;
            As[alk+2][alr] = pa.z;
            As[alk+3][alr] = pa.w;
        }
        if (tid < 192) {
            *(float2*)&Bs[alk+0][2*alr] = make_float2(pb.x, pb.x);
            *(float2*)&Bs[alk+1][2*alr] = make_float2(pb.y, pb.y);
            *(float2*)&Bs[alk+2][2*alr] = make_float2(pb.z, pb.z);
            *(float2*)&Bs[alk+3][2*alr] = make_float2(pb.w, pb.w);
        }
        __syncthreads();
        if (c + 1 < nch) {
            if (tid < 64)  pa = *(const float4*)(Ag + (size_t)(c+1)*BKc);
            if (tid < 192) pb = *(const float4*)(Wg + (size_t)(c+1)*BKc);
        }
#pragma unroll
        for (int kk = 0; kk < BKc; ++kk) {
            ulonglong2 aq = *(const ulonglong2*)&As[kk][ty*4];
            ull am[2] = {aq.x, aq.y};                 /* m-pairs (2mi,2mi+1) */
            ull bg[3];
#pragma unroll
            for (int g = 0; g < 3; g++)
                bg[g] = *(const ull*)&Bs[kk][2*(g*32 + tx)]; /* dup (b,b)   */
#pragma unroll
            for (int mi = 0; mi < 2; mi++)
#pragma unroll
                for (int g = 0; g < 3; g++) ffma2(acc[mi][g], am[mi], bg[g]);
        }
    }

    /* epilogue: GRU elementwise update */
    const int j = j0 + tx;
    const float bh0 = b_hh[j], bh1 = b_hh[CH + j], bh2 = b_hh[2*CH + j];
#pragma unroll
    for (int mi = 0; mi < 2; mi++) {
        float2 vr = upk(acc[mi][0]);
        float2 vz = upk(acc[mi][1]);
        float2 vn = upk(acc[mi][2]);
#pragma unroll
        for (int half = 0; half < 2; half++) {
            int m = m0 + ty*4 + 2*mi + half;
            float ghr = (half ? vr.y : vr.x) + bh0;
            float ghz = (half ? vz.y : vz.x) + bh1;
            float ghn = (half ? vn.y : vn.x) + bh2;
            int b = m / CP, p = m - b * CP;
            size_t grow = (size_t)(b * CT + t) * CP + p;
            const float* gxr = gx + grow * (3*CH);
            float xr = gxr[j], xz = gxr[CH + j], xn = gxr[2*CH + j];
            float hold = h_in[(size_t)m * CH + j];
            float r = 1.f / (1.f + expf(-(xr + ghr)));
            float z = 1.f / (1.f + expf(-(xz + ghz)));
            float n = tanhf(xn + r * ghn);
            float hnew = (1.f - z) * n + z * hold;
            h_out[(size_t)m * CH + j] = hnew;
            hid[grow * CH + j]       = hnew;
        }
    }
}

/* ---------------- heads -------------------------------------------------- */
__global__ __launch_bounds__(256) void action_head(
    const float* __restrict__ hid, const float* __restrict__ W,
    const float* __restrict__ bias, float* __restrict__ out)
{
    __shared__ float Ws[9 * CH];
    for (int i = threadIdx.x; i < 9 * CH; i += 256) Ws[i] = W[i];
    __syncthreads();
    const int warp = threadIdx.x >> 5, lane = threadIdx.x & 31;
    const int m = blockIdx.x * 8 + warp;
    const float* hr = hid + (size_t)m * CH;
    float p[9];
#pragma unroll
    for (int a = 0; a < 9; a++) p[a] = 0.f;
    for (int kk = 0; kk < CH/32; kk++) {
        int k = lane + 32*kk;
        float v = hr[k];
#pragma unroll
        for (int a = 0; a < 9; a++) p[a] += v * Ws[a*CH + k];
    }
#pragma unroll
    for (int a = 0; a < 9; a++) {
        float s = p[a];
#pragma unroll
        for (int o = 16; o > 0; o >>= 1) s += __shfl_down_sync(0xffffffffu, s, o);
        if (lane == 0) out[(size_t)m * 9 + a] = s + bias[a];
    }
}

__global__ __launch_bounds__(256) void activity_head(
    const float* __restrict__ hid, const float* __restrict__ W,
    const float* __restrict__ bias, float* __restrict__ out)
{
    __shared__ float Ws[8 * CH];
    for (int i = threadIdx.x; i < 8 * CH; i += 256) Ws[i] = W[i];
    __syncthreads();
    const int warp = threadIdx.x >> 5, lane = threadIdx.x & 31;
    const int bt = blockIdx.x * 8 + warp;                 /* (b*T+t) */
    const float* base = hid + (size_t)bt * CP * CH;
    float p[8];
#pragma unroll
    for (int a = 0; a < 8; a++) p[a] = 0.f;
    for (int kk = 0; kk < CH/32; kk++) {
        int k = lane + 32*kk;
        float v = base[k];
#pragma unroll
        for (int pp = 1; pp < CP; pp++) v = fmaxf(v, base[(size_t)pp*CH + k]);
#pragma unroll
        for (int a = 0; a < 8; a++) p[a] += v * Ws[a*CH + k];
    }
#pragma unroll
    for (int a = 0; a < 8; a++) {
        float s = p[a];
#pragma unroll
        for (int o = 16; o > 0; o >>= 1) s += __shfl_down_sync(0xffffffffu, s, o);
        if (lane == 0) out[(size_t)bt * 8 + a] = s + bias[a];
    }
}

__global__ void zero_kernel(float* p, int n) {
    int i = blockIdx.x * 256 + threadIdx.x;
    if (i < n) p[i] = 0.f;
}

/* ---------------- launcher ----------------------------------------------- */
extern "C" void kernel_launch(void* const* d_in, const int* in_sizes, int n_in,
                              void* d_out, int out_size)
{
    const float* feature = (const float*)d_in[0];
    const float* W_embed = (const float*)d_in[1];
    const float* b_embed = (const float*)d_in[2];
    const float* W_ih    = (const float*)d_in[3];
    const float* W_hh    = (const float*)d_in[4];
    const float* b_ih    = (const float*)d_in[5];
    const float* b_hh    = (const float*)d_in[6];
    const float* W_act   = (const float*)d_in[7];
    const float* b_act   = (const float*)d_in[8];
    const float* W_activ = (const float*)d_in[9];
    const float* b_activ = (const float*)d_in[10];
    float* out = (float*)d_out;

    float *px, *pgx, *phid, *ph0, *ph1;
    cudaGetSymbolAddress((void**)&px,   g_x);
    cudaGetSymbolAddress((void**)&pgx,  g_gx);
    cudaGetSymbolAddress((void**)&phid, g_hid);
    cudaGetSymbolAddress((void**)&ph0,  g_h0);
    cudaGetSymbolAddress((void**)&ph1,  g_h1);

    /* h0 = 0 */
    zero_kernel<<<(CBP*CH + 255)/256, 256>>>(ph0, CBP*CH);

    /* x = tanh(feature @ W_embed^T + b_embed)  [15360,1024] */
    gemm_f32x2<<<dim3(CH/BN, CM/BM), 256>>>(feature, W_embed, b_embed, px,
                                            CM, CH, CE, 1);
    /* gx = x @ W_ih^T + b_ih                   [15360,3072] */
    gemm_f32x2<<<dim3(3*CH/BN, CM/BM), 256>>>(px, W_ih, b_ih, pgx,
                                              CM, 3*CH, CH, 0);

    /* GRU scan, double-buffered state */
    float* hin = ph0;
    float* hout = ph1;
    for (int t = 0; t < CT; ++t) {
        gru_step<<<dim3(CH/GN, CBP/GM), 256>>>(hin, hout, pgx, W_hh, b_hh,
                                               phid, t);
        float* tmp = hin; hin = hout; hout = tmp;
    }

    /* heads: action logits [15360,9] then activity logits [1280,8] */
    action_head<<<CM/8, 256>>>(phid, W_act, b_act, out);
    activity_head<<<(CB*CT)/8, 256>>>(phid, W_activ, b_activ,
                                      out + (size_t)CM * 9);
}

// round 7
// speedup vs baseline: 2.1349x; 2.1349x over previous
#include <cuda_runtime.h>
#include <math.h>

typedef unsigned long long ull;

#define CB 32
#define CT 40
#define CP 12
#define CE 2048
#define CH 1024
#define CM (CB*CT*CP)     /* 15360 rows of (b,t,p) */
#define CBP (CB*CP)       /* 384 GRU state rows */

/* ---------------- scratch (device globals; no allocation allowed) -------- */
__device__ float g_x  [CM * CH];        /* embed output, 63 MB  */
__device__ float g_gx [CM * 3 * CH];    /* input gates, 189 MB  */
__device__ float g_hid[CM * CH];        /* all hiddens, 63 MB   */
__device__ float g_h0 [CBP * CH];
__device__ float g_h1 [CBP * CH];

/* ---------------- packed fp32x2 FMA (Blackwell FFMA2) -------------------- */
__device__ __forceinline__ void ffma2(ull& d, ull a, ull b) {
    asm("fma.rn.f32x2 %0, %1, %2, %0;" : "+l"(d) : "l"(a), "l"(b));
}
__device__ __forceinline__ float2 upk(ull v) {
    return *reinterpret_cast<float2*>(&v);
}

/* ================= big GEMM: C[m,n] = act(A[m,:]·W[n,:] + b[n]) ==========
 * Tile 128x128, BK=8, 256 threads. Accumulators paired along M:
 * acc[mp][n] = (out[2mp], out[2mp+1]) for col n. A natural in smem
 * (broadcast LDS.128), W duplicated so (w,w) pairs come as one
 * conflict-free LDS.128 covering two adjacent columns.
 * Per kk: 2 a-LDS.128 + 4 b-LDS.128 + 32 FFMA2 (84% FFMA2 density).
 * Thread tx owns cols {32q + 2tx, 32q + 2tx + 1}, q=0..3 (16B-stride
 * addresses -> conflict free).                                           */
#define BM 128
#define BN 128
#define BKc 8

__global__ __launch_bounds__(256) void gemm_f32x2(
    const float* __restrict__ A, const float* __restrict__ W,
    const float* __restrict__ bias, float* __restrict__ C,
    int N, int K, int act)
{
    __shared__ __align__(16) float As[BKc][BM + 4];      /* natural      */
    __shared__ __align__(16) float Bs[BKc][2*BN + 8];    /* dup (w,w)    */

    const int tid = threadIdx.x;
    const int tx  = tid & 15;          /* col group            */
    const int ty  = tid >> 4;          /* rows ty*8..ty*8+7    */
    const int lr  = tid >> 1;          /* loader row 0..127    */
    const int lk  = (tid & 1) << 2;    /* loader k offset      */

    const float* Ag = A + (size_t)(blockIdx.y * BM + lr) * K + lk;
    const float* Wg = W + (size_t)(blockIdx.x * BN + lr) * K + lk;

    ull acc[4][8];
#pragma unroll
    for (int i = 0; i < 4; i++)
#pragma unroll
        for (int j = 0; j < 8; j++) acc[i][j] = 0ULL;

    float4 pa = *(const float4*)Ag;
    float4 pb = *(const float4*)Wg;

    const int nch = K / BKc;
    for (int c = 0; c < nch; ++c) {
        __syncthreads();
        As[lk+0][lr] = pa.x;
        As[lk+1][lr] = pa.y;
        As[lk+2][lr] = pa.z;
        As[lk+3][lr] = pa.w;
        *(float2*)&Bs[lk+0][2*lr] = make_float2(pb.x, pb.x);
        *(float2*)&Bs[lk+1][2*lr] = make_float2(pb.y, pb.y);
        *(float2*)&Bs[lk+2][2*lr] = make_float2(pb.z, pb.z);
        *(float2*)&Bs[lk+3][2*lr] = make_float2(pb.w, pb.w);
        __syncthreads();
        if (c + 1 < nch) {                 /* prefetch next chunk to regs */
            pa = *(const float4*)(Ag + (size_t)(c+1)*BKc);
            pb = *(const float4*)(Wg + (size_t)(c+1)*BKc);
        }
#pragma unroll
        for (int kk = 0; kk < BKc; ++kk) {
            ulonglong2 a0 = *(const ulonglong2*)&As[kk][ty*8];
            ulonglong2 a1 = *(const ulonglong2*)&As[kk][ty*8 + 4];
            ull am[4] = {a0.x, a0.y, a1.x, a1.y};
            ull bd[8];
#pragma unroll
            for (int q = 0; q < 4; q++) {
                ulonglong2 bq = *(const ulonglong2*)&Bs[kk][q*64 + 4*tx];
                bd[2*q]   = bq.x;
                bd[2*q+1] = bq.y;
            }
#pragma unroll
            for (int mp = 0; mp < 4; mp++)
#pragma unroll
                for (int n = 0; n < 8; n++) ffma2(acc[mp][n], am[mp], bd[n]);
        }
    }

    /* epilogue: acc[mp][2q+jj] = (row 2mp, row 2mp+1) at col 32q+2tx+jj */
    const int colb = blockIdx.x * BN;
    float2 bb[4];
#pragma unroll
    for (int q = 0; q < 4; q++)
        bb[q] = *(const float2*)&bias[colb + 32*q + 2*tx];
#pragma unroll
    for (int mp = 0; mp < 4; mp++) {
#pragma unroll
        for (int half = 0; half < 2; half++) {
            int row = blockIdx.y * BM + ty*8 + 2*mp + half;
            float* Cr = C + (size_t)row * N + colb;
#pragma unroll
            for (int q = 0; q < 4; q++) {
                float2 e = upk(acc[mp][2*q]);
                float2 o = upk(acc[mp][2*q+1]);
                float2 v;
                v.x = (half ? e.y : e.x) + bb[q].x;
                v.y = (half ? o.y : o.x) + bb[q].y;
                if (act) { v.x = tanhf(v.x); v.y = tanhf(v.y); }
                *(float2*)&Cr[32*q + 2*tx] = v;
            }
        }
    }
}

/* ================= fused GRU step ========================================
 * Tile: 128 m-rows x 32 j-cols x 3 gates (96 output cols). Grid 32x3 = 96
 * blocks, 256 threads. acc[mp][g][jj] pairs along M; A natural, W dup.
 * Per kk: 2 a-LDS.128 + 3 b-LDS.128 + 24 FFMA2 (83% density).
 * Epilogue applies the GRU update; h double-buffered across steps.        */
#define GBM 128

__global__ __launch_bounds__(256) void gru_step(
    const float* __restrict__ h_in, float* __restrict__ h_out,
    const float* __restrict__ gx, const float* __restrict__ W_hh,
    const float* __restrict__ b_hh, float* __restrict__ hid, int t)
{
    __shared__ __align__(16) float As[BKc][GBM + 4];     /* h, natural    */
    __shared__ __align__(16) float Bs[BKc][2*96 + 8];    /* W, dup (w,w)  */

    const int tid = threadIdx.x;
    const int tx  = tid & 15;          /* j pair: cols 2tx, 2tx+1       */
    const int ty  = tid >> 4;          /* rows ty*8..+7                 */
    const int m0  = blockIdx.y * GBM;
    const int j0  = blockIdx.x * 32;

    const int lr = tid >> 1, lk = (tid & 1) << 2;
    const float* Ag = h_in + (size_t)(m0 + lr) * CH + lk;          /* 256 thr */
    const float* Wg;
    {
        int g = lr >> 5;                                           /* tid<192 */
        int j = j0 + (lr & 31);
        Wg = W_hh + (size_t)(g * CH + j) * CH + lk;
    }

    ull acc[4][3][2];
#pragma unroll
    for (int i = 0; i < 4; i++)
#pragma unroll
        for (int g = 0; g < 3; g++) { acc[i][g][0] = 0ULL; acc[i][g][1] = 0ULL; }

    float4 pa = *(const float4*)Ag;
    float4 pb;
    if (tid < 192) pb = *(const float4*)Wg;

    const int nch = CH / BKc;   /* 128 */
    for (int c = 0; c < nch; ++c) {
        __syncthreads();
        As[lk+0][lr] = pa.x;
        As[lk+1][lr] = pa.y;
        As[lk+2][lr] = pa.z;
        As[lk+3][lr] = pa.w;
        if (tid < 192) {
            *(float2*)&Bs[lk+0][2*lr] = make_float2(pb.x, pb.x);
            *(float2*)&Bs[lk+1][2*lr] = make_float2(pb.y, pb.y);
            *(float2*)&Bs[lk+2][2*lr] = make_float2(pb.z, pb.z);
            *(float2*)&Bs[lk+3][2*lr] = make_float2(pb.w, pb.w);
        }
        __syncthreads();
        if (c + 1 < nch) {
            pa = *(const float4*)(Ag + (size_t)(c+1)*BKc);
            if (tid < 192) pb = *(const float4*)(Wg + (size_t)(c+1)*BKc);
        }
#pragma unroll
        for (int kk = 0; kk < BKc; ++kk) {
            ulonglong2 a0 = *(const ulonglong2*)&As[kk][ty*8];
            ulonglong2 a1 = *(const ulonglong2*)&As[kk][ty*8 + 4];
            ull am[4] = {a0.x, a0.y, a1.x, a1.y};
            ull bd[3][2];
#pragma unroll
            for (int g = 0; g < 3; g++) {
                ulonglong2 bq = *(const ulonglong2*)&Bs[kk][g*64 + 4*tx];
                bd[g][0] = bq.x;
                bd[g][1] = bq.y;
            }
#pragma unroll
            for (int mp = 0; mp < 4; mp++)
#pragma unroll
                for (int g = 0; g < 3; g++) {
                    ffma2(acc[mp][g][0], am[mp], bd[g][0]);
                    ffma2(acc[mp][g][1], am[mp], bd[g][1]);
                }
        }
    }

    /* epilogue: GRU elementwise update (8 m-rows x 2 j-cols per thread) */
    const int jb = j0 + 2*tx;
    float2 bhr = *(const float2*)&b_hh[jb];
    float2 bhz = *(const float2*)&b_hh[CH + jb];
    float2 bhn = *(const float2*)&b_hh[2*CH + jb];
#pragma unroll
    for (int mp = 0; mp < 4; mp++) {
        float2 r0 = upk(acc[mp][0][0]), r1 = upk(acc[mp][0][1]);
        float2 z0 = upk(acc[mp][1][0]), z1 = upk(acc[mp][1][1]);
        float2 n0 = upk(acc[mp][2][0]), n1 = upk(acc[mp][2][1]);
#pragma unroll
        for (int half = 0; half < 2; half++) {
            int m = m0 + ty*8 + 2*mp + half;
            int b = m / CP, p = m - b * CP;
            size_t grow = (size_t)(b * CT + t) * CP + p;
            const float* gxr = gx + grow * (3*CH);
            float2 xr = *(const float2*)&gxr[jb];
            float2 xz = *(const float2*)&gxr[CH + jb];
            float2 xn = *(const float2*)&gxr[2*CH + jb];
            float2 hold = *(const float2*)&h_in[(size_t)m * CH + jb];
            float ghr0 = (half ? r0.y : r0.x) + bhr.x;
            float ghr1 = (half ? r1.y : r1.x) + bhr.y;
            float ghz0 = (half ? z0.y : z0.x) + bhz.x;
            float ghz1 = (half ? z1.y : z1.x) + bhz.y;
            float ghn0 = (half ? n0.y : n0.x) + bhn.x;
            float ghn1 = (half ? n1.y : n1.x) + bhn.y;
            float r_0 = 1.f / (1.f + expf(-(xr.x + ghr0)));
            float r_1 = 1.f / (1.f + expf(-(xr.y + ghr1)));
            float z_0 = 1.f / (1.f + expf(-(xz.x + ghz0)));
            float z_1 = 1.f / (1.f + expf(-(xz.y + ghz1)));
            float n_0 = tanhf(xn.x + r_0 * ghn0);
            float n_1 = tanhf(xn.y + r_1 * ghn1);
            float2 hn;
            hn.x = (1.f - z_0) * n_0 + z_0 * hold.x;
            hn.y = (1.f - z_1) * n_1 + z_1 * hold.y;
            *(float2*)&h_out[(size_t)m * CH + jb] = hn;
            *(float2*)&hid[grow * CH + jb]        = hn;
        }
    }
}

/* ---------------- heads -------------------------------------------------- */
__global__ __launch_bounds__(256) void action_head(
    const float* __restrict__ hid, const float* __restrict__ W,
    const float* __restrict__ bias, float* __restrict__ out)
{
    __shared__ float Ws[9 * CH];
    for (int i = threadIdx.x; i < 9 * CH; i += 256) Ws[i] = W[i];
    __syncthreads();
    const int warp = threadIdx.x >> 5, lane = threadIdx.x & 31;
    const int m = blockIdx.x * 8 + warp;
    const float* hr = hid + (size_t)m * CH;
    float p[9];
#pragma unroll
    for (int a = 0; a < 9; a++) p[a] = 0.f;
    for (int kk = 0; kk < CH/32; kk++) {
        int k = lane + 32*kk;
        float v = hr[k];
#pragma unroll
        for (int a = 0; a < 9; a++) p[a] += v * Ws[a*CH + k];
    }
#pragma unroll
    for (int a = 0; a < 9; a++) {
        float s = p[a];
#pragma unroll
        for (int o = 16; o > 0; o >>= 1) s += __shfl_down_sync(0xffffffffu, s, o);
        if (lane == 0) out[(size_t)m * 9 + a] = s + bias[a];
    }
}

__global__ __launch_bounds__(256) void activity_head(
    const float* __restrict__ hid, const float* __restrict__ W,
    const float* __restrict__ bias, float* __restrict__ out)
{
    __shared__ float Ws[8 * CH];
    for (int i = threadIdx.x; i < 8 * CH; i += 256) Ws[i] = W[i];
    __syncthreads();
    const int warp = threadIdx.x >> 5, lane = threadIdx.x & 31;
    const int bt = blockIdx.x * 8 + warp;                 /* (b*T+t) */
    const float* base = hid + (size_t)bt * CP * CH;
    float p[8];
#pragma unroll
    for (int a = 0; a < 8; a++) p[a] = 0.f;
    for (int kk = 0; kk < CH/32; kk++) {
        int k = lane + 32*kk;
        float v = base[k];
#pragma unroll
        for (int pp = 1; pp < CP; pp++) v = fmaxf(v, base[(size_t)pp*CH + k]);
#pragma unroll
        for (int a = 0; a < 8; a++) p[a] += v * Ws[a*CH + k];
    }
#pragma unroll
    for (int a = 0; a < 8; a++) {
        float s = p[a];
#pragma unroll
        for (int o = 16; o > 0; o >>= 1) s += __shfl_down_sync(0xffffffffu, s, o);
        if (lane == 0) out[(size_t)bt * 8 + a] = s + bias[a];
    }
}

__global__ void zero_kernel(float* p, int n) {
    int i = blockIdx.x * 256 + threadIdx.x;
    if (i < n) p[i] = 0.f;
}

/* ---------------- launcher ----------------------------------------------- */
extern "C" void kernel_launch(void* const* d_in, const int* in_sizes, int n_in,
                              void* d_out, int out_size)
{
    const float* feature = (const float*)d_in[0];
    const float* W_embed = (const float*)d_in[1];
    const float* b_embed = (const float*)d_in[2];
    const float* W_ih    = (const float*)d_in[3];
    const float* W_hh    = (const float*)d_in[4];
    const float* b_ih    = (const float*)d_in[5];
    const float* b_hh    = (const float*)d_in[6];
    const float* W_act   = (const float*)d_in[7];
    const float* b_act   = (const float*)d_in[8];
    const float* W_activ = (const float*)d_in[9];
    const float* b_activ = (const float*)d_in[10];
    float* out = (float*)d_out;

    float *px, *pgx, *phid, *ph0, *ph1;
    cudaGetSymbolAddress((void**)&px,   g_x);
    cudaGetSymbolAddress((void**)&pgx,  g_gx);
    cudaGetSymbolAddress((void**)&phid, g_hid);
    cudaGetSymbolAddress((void**)&ph0,  g_h0);
    cudaGetSymbolAddress((void**)&ph1,  g_h1);

    /* h0 = 0 */
    zero_kernel<<<(CBP*CH + 255)/256, 256>>>(ph0, CBP*CH);

    /* x = tanh(feature @ W_embed^T + b_embed)  [15360,1024] */
    gemm_f32x2<<<dim3(CH/BN, CM/BM), 256>>>(feature, W_embed, b_embed, px,
                                            CH, CE, 1);
    /* gx = x @ W_ih^T + b_ih                   [15360,3072] */
    gemm_f32x2<<<dim3(3*CH/BN, CM/BM), 256>>>(px, W_ih, b_ih, pgx,
                                              3*CH, CH, 0);

    /* GRU scan, double-buffered state */
    float* hin = ph0;
    float* hout = ph1;
    for (int t = 0; t < CT; ++t) {
        gru_step<<<dim3(CH/32, CBP/GBM), 256>>>(hin, hout, pgx, W_hh, b_hh,
                                                phid, t);
        float* tmp = hin; hin = hout; hout = tmp;
    }

    /* heads: action logits [15360,9] then activity logits [1280,8] */
    action_head<<<CM/8, 256>>>(phid, W_act, b_act, out);
    activity_head<<<(CB*CT)/8, 256>>>(phid, W_activ, b_activ,
                                      out + (size_t)CM * 9);
}